// round 7
// baseline (speedup 1.0000x reference)
#include <cuda_runtime.h>
#include <cuda_bf16.h>
#include <cstddef>
#include <cstdint>

#define NN     3072
#define IND    128
#define HEADS  4
#define ODIM   64
#define EDIM   8
#define HD     256        // HEADS*ODIM
#define TI     32         // i-rows per block
#define JC     16         // j per chunk (shrunk for occupancy 3)
#define JPAD   20         // row stride for w: 80B, 16B-aligned
#define JSPLIT 8
#define JRANGE (NN / JSPLIT)   // 384
#define NCHUNK (JRANGE / JC)   // 24
#define EFU    (JC * EDIM)     // 128 floats of ef per i-row per chunk

typedef unsigned long long u64;

// ---------------- scratch (static device globals: no runtime allocs) -------
__device__ __align__(256) float  g_h[NN * HD];                 // 3 MB
__device__ __align__(256) float4 g_ssrc[NN];
__device__ __align__(256) float4 g_sdst[NN];
__device__ __align__(256) float  g_pacc[JSPLIT][NN * HD];      // 25.2 MB
__device__ __align__(256) float  g_pden[JSPLIT][NN * HEADS];

// ---------------- packed fp32x2 + cp.async helpers -------------------------
__device__ __forceinline__ void ffma2(u64& d, u64 a, u64 b) {
    asm("fma.rn.f32x2 %0, %1, %2, %3;" : "=l"(d) : "l"(a), "l"(b), "l"(d));
}
__device__ __forceinline__ u64 pack2(float x) {
    u64 r; asm("mov.b64 %0, {%1, %1};" : "=l"(r) : "f"(x)); return r;
}
__device__ __forceinline__ void cpa16(uint32_t s, const void* g) {
    asm volatile("cp.async.cg.shared.global [%0], [%1], 16;" :: "r"(s), "l"(g));
}
#define CP_COMMIT() asm volatile("cp.async.commit_group;")
#define CP_WAIT1()  asm volatile("cp.async.wait_group 1;" ::: "memory")

// ---------------- dynamic smem layout for k_attn ---------------------------
struct __align__(16) SmemAttn {
    float  ef[2][TI][EFU];       // 32 KB : double-buffered edge_feats tiles
    int    adjb[2][TI][JC];      // 4 KB  : double-buffered adjacency tiles
    float  w[HEADS][TI][JPAD];   // 10 KB : attention weights (single buffer)
    float4 sdst[JRANGE];         // 6 KB  : s_dst for this j-split
    float4 ssrc[TI];
    float4 epw[EDIM];
    float4 epb;
};                               // ~53.3 KB -> 3 blocks/SM

// ---------------- kernel 1: h = x @ W  (3072x128 @ 128x256) ---------------
__global__ __launch_bounds__(256) void k_proj(const float* __restrict__ x,
                                              const float* __restrict__ W) {
    __shared__ float4 xs4[16 * IND / 4];
    const int t  = threadIdx.x;            // output column 0..255
    const int i0 = blockIdx.x * 16;

    const float4* xg4 = (const float4*)(x + (size_t)i0 * IND);
#pragma unroll
    for (int k = 0; k < 2; k++) xs4[t + 256 * k] = xg4[t + 256 * k];
    __syncthreads();

    float acc[16];
#pragma unroll
    for (int r = 0; r < 16; r++) acc[r] = 0.f;

    for (int k4 = 0; k4 < IND / 4; k4++) {
        const float w0 = W[(k4 * 4 + 0) * HD + t];
        const float w1 = W[(k4 * 4 + 1) * HD + t];
        const float w2 = W[(k4 * 4 + 2) * HD + t];
        const float w3 = W[(k4 * 4 + 3) * HD + t];
#pragma unroll
        for (int r = 0; r < 16; r++) {
            const float4 xv = xs4[r * (IND / 4) + k4];
            acc[r] += xv.x * w0 + xv.y * w1 + xv.z * w2 + xv.w * w3;
        }
    }
#pragma unroll
    for (int r = 0; r < 16; r++) g_h[(size_t)(i0 + r) * HD + t] = acc[r];
}

// ---------------- kernel 2: s_src / s_dst ---------------------------------
__global__ __launch_bounds__(256) void k_scores(const float* __restrict__ a_src,
                                                const float* __restrict__ a_dst) {
    const int tid = blockIdx.x * blockDim.x + threadIdx.x;   // N*H threads
    const int n = tid >> 2, h = tid & 3;
    const float4* hv = (const float4*)(g_h + (size_t)n * HD + h * ODIM);
    const float4* as = (const float4*)(a_src + h * ODIM);
    const float4* ad = (const float4*)(a_dst + h * ODIM);
    float ss = 0.f, sd = 0.f;
#pragma unroll
    for (int q = 0; q < ODIM / 4; q++) {
        const float4 hq = hv[q], aq = as[q], dq = ad[q];
        ss += hq.x * aq.x + hq.y * aq.y + hq.z * aq.z + hq.w * aq.w;
        sd += hq.x * dq.x + hq.y * dq.y + hq.z * dq.z + hq.w * dq.w;
    }
    ((float*)g_ssrc)[tid] = ss;
    ((float*)g_sdst)[tid] = sd;
}

// ---------------- cp.async prefetch of one (ef, adj) chunk -----------------
__device__ __forceinline__ void prefetch_chunk(SmemAttn* S, int buf, int i0, int j0,
                                               const float* __restrict__ ef,
                                               const int*   __restrict__ adj, int t) {
    // ef tile: 32 i-rows x 512B = 1024 x 16B units
#pragma unroll
    for (int k = 0; k < 4; k++) {
        const int u  = t + k * 256;
        const int i  = u >> 5;             // 32 units per row
        const int uo = u & 31;
        const uint32_t dst = (uint32_t)__cvta_generic_to_shared(&S->ef[buf][i][uo * 4]);
        cpa16(dst, ef + ((size_t)(i0 + i) * NN + j0) * EDIM + uo * 4);
    }
    // adj tile: 32 x 16 ints = 128 x 16B units
    if (t < 128) {
        const int i  = t >> 2;
        const int j4 = t & 3;
        const uint32_t dst = (uint32_t)__cvta_generic_to_shared(&S->adjb[buf][i][j4 * 4]);
        cpa16(dst, adj + (size_t)(i0 + i) * NN + j0 + j4 * 4);
    }
}

// ---------------- kernel 3: fused attention, cp.async pipelined, occ 3 -----
__global__ __launch_bounds__(256, 3) void k_attn(const float* __restrict__ ef,
                                                 const int*   __restrict__ adj,
                                                 const float* __restrict__ ep_w,
                                                 const float* __restrict__ ep_b) {
    extern __shared__ char smem_raw[];
    SmemAttn* S = (SmemAttn*)smem_raw;

    const int t     = threadIdx.x;
    const int i0    = blockIdx.x * TI;
    const int js    = blockIdx.y;
    const int jbase = js * JRANGE;

    // stage small constants + s_dst slice (visible after first barrier)
    if (t < EDIM) S->epw[t] = ((const float4*)ep_w)[t];
    if (t == EDIM) S->epb = *(const float4*)ep_b;
    if (t < TI) S->ssrc[t] = g_ssrc[i0 + t];
    for (int k = t; k < JRANGE; k += 256) S->sdst[k] = g_sdst[jbase + k];

    // kick off chunk 0
    prefetch_chunk(S, 0, i0, jbase, ef, adj, t);
    CP_COMMIT();

    // phase-2 identity: per head a 32x64 C tile, 4 rows x 8 cols per thread
    const int h2  = t >> 6;
    const int s2  = t & 63;
    const int il0 = (s2 >> 3) * 4;
    const int d0  = (s2 & 7) * 8;
    // phase-1 identity: 16 j-lanes x 16 i-rows per pass, 2 passes
    const int jl  = t & 15;
    const int ih  = t >> 4;        // 0..15

    u64 acc2[4][4];
#pragma unroll
    for (int r = 0; r < 4; r++)
#pragma unroll
        for (int q = 0; q < 4; q++) acc2[r][q] = 0ull;
    float pden[2][4];              // per pass (i row), per head
#pragma unroll
    for (int p = 0; p < 2; p++)
#pragma unroll
        for (int h = 0; h < 4; h++) pden[p][h] = 0.f;

    for (int c = 0; c < NCHUNK; c++) {
        const int j0  = jbase + c * JC;
        const int buf = c & 1;

        // prefetch chunk c+1 into the other buffer; commit every iteration
        // so group counts stay aligned (empty group on the last chunk).
        if (c + 1 < NCHUNK)
            prefetch_chunk(S, buf ^ 1, i0, j0 + JC, ef, adj, t);
        CP_COMMIT();
        CP_WAIT1();          // chunk c complete (all but newest group)
        __syncthreads();     // syncA: chunk c visible; also fences w reuse

        // ---- phase 1: w = adj ? exp(leaky(ssrc+sdst+edge@epw+epb)) : 0
        const float4 epb4 = S->epb;
#pragma unroll
        for (int p = 0; p < 2; p++) {
            const int i  = p * 16 + ih;
            const float4 ea = *(const float4*)&S->ef[buf][i][jl * 8];
            const float4 eb = *(const float4*)&S->ef[buf][i][jl * 8 + 4];
            const int    am = S->adjb[buf][i][jl];
            const float4 sd4 = S->sdst[c * JC + jl];
            const float4 ss4 = S->ssrc[i];

            float vx = epb4.x + ss4.x + sd4.x;
            float vy = epb4.y + ss4.y + sd4.y;
            float vz = epb4.z + ss4.z + sd4.z;
            float vw = epb4.w + ss4.w + sd4.w;
            float4 we;
            we = S->epw[0]; vx += ea.x * we.x; vy += ea.x * we.y; vz += ea.x * we.z; vw += ea.x * we.w;
            we = S->epw[1]; vx += ea.y * we.x; vy += ea.y * we.y; vz += ea.y * we.z; vw += ea.y * we.w;
            we = S->epw[2]; vx += ea.z * we.x; vy += ea.z * we.y; vz += ea.z * we.z; vw += ea.z * we.w;
            we = S->epw[3]; vx += ea.w * we.x; vy += ea.w * we.y; vz += ea.w * we.z; vw += ea.w * we.w;
            we = S->epw[4]; vx += eb.x * we.x; vy += eb.x * we.y; vz += eb.x * we.z; vw += eb.x * we.w;
            we = S->epw[5]; vx += eb.y * we.x; vy += eb.y * we.y; vz += eb.y * we.z; vw += eb.y * we.w;
            we = S->epw[6]; vx += eb.z * we.x; vy += eb.z * we.y; vz += eb.z * we.z; vw += eb.z * we.w;
            we = S->epw[7]; vx += eb.w * we.x; vy += eb.w * we.y; vz += eb.w * we.z; vw += eb.w * we.w;

            vx = fmaxf(vx, 0.2f * vx);
            vy = fmaxf(vy, 0.2f * vy);
            vz = fmaxf(vz, 0.2f * vz);
            vw = fmaxf(vw, 0.2f * vw);

            const float w0 = am ? __expf(vx) : 0.f;
            const float w1 = am ? __expf(vy) : 0.f;
            const float w2 = am ? __expf(vz) : 0.f;
            const float w3 = am ? __expf(vw) : 0.f;

            S->w[0][i][jl] = w0;
            S->w[1][i][jl] = w1;
            S->w[2][i][jl] = w2;
            S->w[3][i][jl] = w3;
            pden[p][0] += w0; pden[p][1] += w1; pden[p][2] += w2; pden[p][3] += w3;
        }
        __syncthreads();     // syncB: w fully written

        // ---- phase 2: acc[i,d] += w[i,j] * h[j,h2,d]   (packed f32x2 FMA)
#pragma unroll
        for (int jq = 0; jq < JC; jq += 4) {
            const float4 wq0 = *(const float4*)&S->w[h2][il0 + 0][jq];
            const float4 wq1 = *(const float4*)&S->w[h2][il0 + 1][jq];
            const float4 wq2 = *(const float4*)&S->w[h2][il0 + 2][jq];
            const float4 wq3 = *(const float4*)&S->w[h2][il0 + 3][jq];
#pragma unroll
            for (int jj = 0; jj < 4; jj++) {
                const ulonglong2* b =
                    (const ulonglong2*)(g_h + (size_t)(j0 + jq + jj) * HD + h2 * ODIM + d0);
                const ulonglong2 p0 = b[0];
                const ulonglong2 p1 = b[1];
                u64 wp;
                wp = pack2((&wq0.x)[jj]);
                ffma2(acc2[0][0], wp, p0.x); ffma2(acc2[0][1], wp, p0.y);
                ffma2(acc2[0][2], wp, p1.x); ffma2(acc2[0][3], wp, p1.y);
                wp = pack2((&wq1.x)[jj]);
                ffma2(acc2[1][0], wp, p0.x); ffma2(acc2[1][1], wp, p0.y);
                ffma2(acc2[1][2], wp, p1.x); ffma2(acc2[1][3], wp, p1.y);
                wp = pack2((&wq2.x)[jj]);
                ffma2(acc2[2][0], wp, p0.x); ffma2(acc2[2][1], wp, p0.y);
                ffma2(acc2[2][2], wp, p1.x); ffma2(acc2[2][3], wp, p1.y);
                wp = pack2((&wq3.x)[jj]);
                ffma2(acc2[3][0], wp, p0.x); ffma2(acc2[3][1], wp, p0.y);
                ffma2(acc2[3][2], wp, p1.x); ffma2(acc2[3][3], wp, p1.y);
            }
        }
        // no trailing barrier: w is next written only after syncA of c+1.
    }

    // ---- write additive partials (still packed)
    float* pa = g_pacc[js];
#pragma unroll
    for (int r = 0; r < 4; r++) {
        ulonglong2* dst =
            (ulonglong2*)(pa + (size_t)(i0 + il0 + r) * HD + h2 * ODIM + d0);
        ulonglong2 o0; o0.x = acc2[r][0]; o0.y = acc2[r][1];
        ulonglong2 o1; o1.x = acc2[r][2]; o1.y = acc2[r][3];
        dst[0] = o0;
        dst[1] = o1;
    }
    // denom: 16 j-lanes per i-row -> half-warp reduce, lane jl==0 writes
#pragma unroll
    for (int p = 0; p < 2; p++)
#pragma unroll
        for (int h = 0; h < 4; h++) {
            float v = pden[p][h];
#pragma unroll
            for (int o = 8; o; o >>= 1) v += __shfl_xor_sync(0xffffffffu, v, o);
            if (jl == 0)
                g_pden[js][(i0 + p * 16 + ih) * HEADS + h] = v;
        }
}

// ---------------- kernel 4: combine + normalize + layernorm ----------------
__global__ __launch_bounds__(256) void k_final(const float* __restrict__ gamma,
                                               const float* __restrict__ beta,
                                               float* __restrict__ out) {
    __shared__ float rs[4][2], rq[4][2];
    __shared__ float mean_s[4], rstd_s[4];

    const int t = threadIdx.x;
    const int r = t >> 6;          // row within block
    const int s = t & 63;          // float4 index within row (0..63)
    const int n = blockIdx.x * 4 + r;

    float4 v = make_float4(0.f, 0.f, 0.f, 0.f);
#pragma unroll
    for (int sp = 0; sp < JSPLIT; sp++) {
        const float4 p = *(const float4*)&g_pacc[sp][(size_t)n * HD + s * 4];
        v.x += p.x; v.y += p.y; v.z += p.z; v.w += p.w;
    }
    const int h = s >> 4;          // head of this float4
    float den = 0.f;
#pragma unroll
    for (int sp = 0; sp < JSPLIT; sp++) den += g_pden[sp][n * HEADS + h];
    const float inv = __frcp_rn(den);
    v.x *= inv; v.y *= inv; v.z *= inv; v.w *= inv;

    float sum = v.x + v.y + v.z + v.w;
    float sq  = v.x * v.x + v.y * v.y + v.z * v.z + v.w * v.w;
#pragma unroll
    for (int o = 16; o; o >>= 1) {
        sum += __shfl_xor_sync(0xffffffffu, sum, o);
        sq  += __shfl_xor_sync(0xffffffffu, sq, o);
    }
    const int half = (t >> 5) & 1;
    if ((t & 31) == 0) { rs[r][half] = sum; rq[r][half] = sq; }
    __syncthreads();
    if (s == 0) {
        const float S = rs[r][0] + rs[r][1];
        const float Q = rq[r][0] + rq[r][1];
        const float m = S * (1.f / HD);
        const float var = Q * (1.f / HD) - m * m;
        mean_s[r] = m;
        rstd_s[r] = rsqrtf(var + 1e-5f);
    }
    __syncthreads();
    const float m   = mean_s[r];
    const float rsd = rstd_s[r];
    const float4 g = ((const float4*)gamma)[s];
    const float4 b = ((const float4*)beta)[s];
    float4 o;
    o.x = (v.x - m) * rsd * g.x + b.x;
    o.y = (v.y - m) * rsd * g.y + b.y;
    o.z = (v.z - m) * rsd * g.z + b.z;
    o.w = (v.w - m) * rsd * g.w + b.w;
    ((float4*)out)[(size_t)n * (HD / 4) + s] = o;
}

// ---------------- launch ----------------------------------------------------
extern "C" void kernel_launch(void* const* d_in, const int* in_sizes, int n_in,
                              void* d_out, int out_size) {
    const float* x      = (const float*)d_in[0];
    const int*   adj    = (const int*)  d_in[1];
    const float* ef     = (const float*)d_in[2];
    const float* W      = (const float*)d_in[3];
    const float* a_src  = (const float*)d_in[4];
    const float* a_dst  = (const float*)d_in[5];
    const float* ep_w   = (const float*)d_in[6];
    const float* ep_b   = (const float*)d_in[7];
    const float* gamma  = (const float*)d_in[8];
    const float* beta   = (const float*)d_in[9];
    float* out = (float*)d_out;

    const int smem_bytes = (int)sizeof(SmemAttn);   // ~53.3 KB
    cudaFuncSetAttribute(k_attn, cudaFuncAttributeMaxDynamicSharedMemorySize,
                         smem_bytes);

    k_proj  <<<NN / 16, 256>>>(x, W);
    k_scores<<<(NN * HEADS) / 256, 256>>>(a_src, a_dst);
    k_attn  <<<dim3(NN / TI, JSPLIT), 256, smem_bytes>>>(ef, adj, ep_w, ep_b);
    k_final <<<NN / 4, 256>>>(gamma, beta, out);
}

// round 8
// speedup vs baseline: 1.4663x; 1.4663x over previous
#include <cuda_runtime.h>
#include <cuda_bf16.h>
#include <cstddef>
#include <cstdint>

#define NN     3072
#define IND    128
#define HEADS  4
#define ODIM   64
#define EDIM   8
#define HD     256        // HEADS*ODIM
#define TI     64         // i-rows per block
#define JC     16         // j per chunk
#define WROW   17         // w row stride (floats): 8*17 mod 32 = 8 -> bank-clean
#define JSPLIT 6
#define JRANGE (NN / JSPLIT)   // 512
#define NCHUNK (JRANGE / JC)   // 32

typedef unsigned long long u64;

// ---------------- scratch (static device globals: no runtime allocs) -------
__device__ __align__(256) float  g_h[NN * HD];                 // 3 MB
__device__ __align__(256) float4 g_ssrc[NN];
__device__ __align__(256) float4 g_sdst[NN];
__device__ __align__(256) float  g_pacc[JSPLIT][NN * HD];      // 18.9 MB
__device__ __align__(256) float  g_pden[JSPLIT][NN * HEADS];

// ---------------- packed fp32x2 + cp.async helpers -------------------------
__device__ __forceinline__ void ffma2(u64& d, u64 a, u64 b) {
    asm("fma.rn.f32x2 %0, %1, %2, %3;" : "=l"(d) : "l"(a), "l"(b), "l"(d));
}
__device__ __forceinline__ u64 pack2(float x) {
    u64 r; asm("mov.b64 %0, {%1, %1};" : "=l"(r) : "f"(x)); return r;
}
__device__ __forceinline__ void cpa16(uint32_t s, const void* g) {
    asm volatile("cp.async.cg.shared.global [%0], [%1], 16;" :: "r"(s), "l"(g));
}
#define CP_COMMIT() asm volatile("cp.async.commit_group;")
#define CP_WAIT0()  asm volatile("cp.async.wait_group 0;" ::: "memory")

// ---------------- dynamic smem layout for k_attn ---------------------------
struct __align__(16) SmemAttn {
    float  ef[TI][JC * EDIM];      // 32 KB : edge_feats tile (single buffer)
    float  hs[JC * HD];            // 16 KB : h tile, chunk-permuted layout
    int    adjb[TI][JC];           // 4 KB  : adjacency tile
    float  w[HEADS][TI * WROW + 8];// 17.2 KB: attention weights
    float4 sdst[JRANGE];           // 8 KB
    float4 ssrc[TI];               // 1 KB
    float4 epw[EDIM];
    float4 epb;
};                                 // ~78.5 KB -> 2 blocks/SM

// ---------------- kernel 1: h = x @ W  (3072x128 @ 128x256) ---------------
__global__ __launch_bounds__(256) void k_proj(const float* __restrict__ x,
                                              const float* __restrict__ W) {
    __shared__ float4 xs4[16 * IND / 4];
    const int t  = threadIdx.x;
    const int i0 = blockIdx.x * 16;

    const float4* xg4 = (const float4*)(x + (size_t)i0 * IND);
#pragma unroll
    for (int k = 0; k < 2; k++) xs4[t + 256 * k] = xg4[t + 256 * k];
    __syncthreads();

    float acc[16];
#pragma unroll
    for (int r = 0; r < 16; r++) acc[r] = 0.f;

    for (int k4 = 0; k4 < IND / 4; k4++) {
        const float w0 = W[(k4 * 4 + 0) * HD + t];
        const float w1 = W[(k4 * 4 + 1) * HD + t];
        const float w2 = W[(k4 * 4 + 2) * HD + t];
        const float w3 = W[(k4 * 4 + 3) * HD + t];
#pragma unroll
        for (int r = 0; r < 16; r++) {
            const float4 xv = xs4[r * (IND / 4) + k4];
            acc[r] += xv.x * w0 + xv.y * w1 + xv.z * w2 + xv.w * w3;
        }
    }
#pragma unroll
    for (int r = 0; r < 16; r++) g_h[(size_t)(i0 + r) * HD + t] = acc[r];
}

// ---------------- kernel 2: s_src / s_dst ---------------------------------
__global__ __launch_bounds__(256) void k_scores(const float* __restrict__ a_src,
                                                const float* __restrict__ a_dst) {
    const int tid = blockIdx.x * blockDim.x + threadIdx.x;
    const int n = tid >> 2, h = tid & 3;
    const float4* hv = (const float4*)(g_h + (size_t)n * HD + h * ODIM);
    const float4* as = (const float4*)(a_src + h * ODIM);
    const float4* ad = (const float4*)(a_dst + h * ODIM);
    float ss = 0.f, sd = 0.f;
#pragma unroll
    for (int q = 0; q < ODIM / 4; q++) {
        const float4 hq = hv[q], aq = as[q], dq = ad[q];
        ss += hq.x * aq.x + hq.y * aq.y + hq.z * aq.z + hq.w * aq.w;
        sd += hq.x * dq.x + hq.y * dq.y + hq.z * dq.z + hq.w * dq.w;
    }
    ((float*)g_ssrc)[tid] = ss;
    ((float*)g_sdst)[tid] = sd;
}

// ---------------- prefetch helpers (cp.async) ------------------------------
__device__ __forceinline__ void prefetch_ef(SmemAttn* S, int i0, int j0,
                                            const float* __restrict__ ef,
                                            const int*   __restrict__ adj, int t) {
    // ef tile: 64 rows x 512B = 2048 x 16B
#pragma unroll
    for (int k = 0; k < 8; k++) {
        const int u  = t + k * 256;
        const int i  = u >> 5;             // 32 units per row
        const int uo = u & 31;
        const uint32_t dst = (uint32_t)__cvta_generic_to_shared(&S->ef[i][uo * 4]);
        cpa16(dst, ef + ((size_t)(i0 + i) * NN + j0) * EDIM + uo * 4);
    }
    // adj tile: 64 x 16 ints = 256 x 16B
    {
        const int i  = t >> 2;
        const int j4 = t & 3;
        const uint32_t dst = (uint32_t)__cvta_generic_to_shared(&S->adjb[i][j4 * 4]);
        cpa16(dst, adj + (size_t)(i0 + i) * NN + j0 + j4 * 4);
    }
}

// h tile with per-head 16B-chunk permutation: chunk k (0..15) -> (k&1)*8+(k>>1)
// so phase-2's p0 (even chunks) and p1 (odd chunks) are each contiguous 128B.
__device__ __forceinline__ void prefetch_h(SmemAttn* S, int j0, int t) {
#pragma unroll
    for (int k = 0; k < 4; k++) {
        const int u   = t + k * 256;
        const int row = u >> 6;            // 64 units per row (1 KB)
        const int cu  = u & 63;
        const int h2  = cu >> 4;
        const int k16 = cu & 15;
        const int pos = (k16 & 1) * 8 + (k16 >> 1);
        const uint32_t dst = (uint32_t)__cvta_generic_to_shared(
            &S->hs[row * HD + h2 * ODIM + pos * 4]);
        cpa16(dst, g_h + (size_t)(j0 + row) * HD + cu * 4);
    }
}

// ---------------- kernel 3: fused attention, fully smem-staged -------------
__global__ __launch_bounds__(256, 2) void k_attn(const float* __restrict__ ef,
                                                 const int*   __restrict__ adj,
                                                 const float* __restrict__ ep_w,
                                                 const float* __restrict__ ep_b) {
    extern __shared__ char smem_raw[];
    SmemAttn* S = (SmemAttn*)smem_raw;

    const int t     = threadIdx.x;
    const int i0    = blockIdx.x * TI;
    const int js    = blockIdx.y;
    const int jbase = js * JRANGE;

    if (t < EDIM) S->epw[t] = ((const float4*)ep_w)[t];
    if (t == EDIM) S->epb = *(const float4*)ep_b;
    if (t < TI) S->ssrc[t] = g_ssrc[i0 + t];
    for (int k = t; k < JRANGE; k += 256) S->sdst[k] = g_sdst[jbase + k];

    prefetch_ef(S, i0, jbase, ef, adj, t);
    CP_COMMIT();

    // phase-2 identity: per head a 64x64 C tile, 8 rows x 8 cols per thread
    const int h2  = t >> 6;
    const int s2  = t & 63;
    const int il0 = (s2 >> 3) * 8;
    const int d8  = (s2 & 7);          // d0 = d8*8
    // phase-1 identity: 16 j-lanes x 16 i-groups, 4 passes
    const int jl  = t & 15;
    const int ih  = t >> 4;

    u64 acc2[8][4];
#pragma unroll
    for (int r = 0; r < 8; r++)
#pragma unroll
        for (int q = 0; q < 4; q++) acc2[r][q] = 0ull;
    float pden[4][4];
#pragma unroll
    for (int p = 0; p < 4; p++)
#pragma unroll
        for (int h = 0; h < 4; h++) pden[p][h] = 0.f;

    for (int c = 0; c < NCHUNK; c++) {
        const int j0 = jbase + c * JC;

        CP_WAIT0();          // ef(c) [and stray h(c-1)] complete
        __syncthreads();     // syncA: ef visible; all phase-2(c-1) readers done

        prefetch_h(S, j0, t);   // safe: h buffer free after syncA
        CP_COMMIT();

        // ---- phase 1: w = adj ? exp(leaky(ssrc+sdst+edge@epw+epb)) : 0
        const float4 epb4 = S->epb;
#pragma unroll
        for (int p = 0; p < 4; p++) {
            const int i  = p * 16 + ih;
            const float4 ea = *(const float4*)&S->ef[i][jl * 8];
            const float4 eb = *(const float4*)&S->ef[i][jl * 8 + 4];
            const int    am = S->adjb[i][jl];
            const float4 sd4 = S->sdst[c * JC + jl];
            const float4 ss4 = S->ssrc[i];

            float vx = epb4.x + ss4.x + sd4.x;
            float vy = epb4.y + ss4.y + sd4.y;
            float vz = epb4.z + ss4.z + sd4.z;
            float vw = epb4.w + ss4.w + sd4.w;
            float4 we;
            we = S->epw[0]; vx += ea.x * we.x; vy += ea.x * we.y; vz += ea.x * we.z; vw += ea.x * we.w;
            we = S->epw[1]; vx += ea.y * we.x; vy += ea.y * we.y; vz += ea.y * we.z; vw += ea.y * we.w;
            we = S->epw[2]; vx += ea.z * we.x; vy += ea.z * we.y; vz += ea.z * we.z; vw += ea.z * we.w;
            we = S->epw[3]; vx += ea.w * we.x; vy += ea.w * we.y; vz += ea.w * we.z; vw += ea.w * we.w;
            we = S->epw[4]; vx += eb.x * we.x; vy += eb.x * we.y; vz += eb.x * we.z; vw += eb.x * we.w;
            we = S->epw[5]; vx += eb.y * we.x; vy += eb.y * we.y; vz += eb.y * we.z; vw += eb.y * we.w;
            we = S->epw[6]; vx += eb.z * we.x; vy += eb.z * we.y; vz += eb.z * we.z; vw += eb.z * we.w;
            we = S->epw[7]; vx += eb.w * we.x; vy += eb.w * we.y; vz += eb.w * we.z; vw += eb.w * we.w;

            vx = fmaxf(vx, 0.2f * vx);
            vy = fmaxf(vy, 0.2f * vy);
            vz = fmaxf(vz, 0.2f * vz);
            vw = fmaxf(vw, 0.2f * vw);

            const float w0 = am ? __expf(vx) : 0.f;
            const float w1 = am ? __expf(vy) : 0.f;
            const float w2 = am ? __expf(vz) : 0.f;
            const float w3 = am ? __expf(vw) : 0.f;

            S->w[0][i * WROW + jl] = w0;
            S->w[1][i * WROW + jl] = w1;
            S->w[2][i * WROW + jl] = w2;
            S->w[3][i * WROW + jl] = w3;
            pden[p][0] += w0; pden[p][1] += w1; pden[p][2] += w2; pden[p][3] += w3;
        }

        CP_WAIT0();          // h(c) complete
        __syncthreads();     // syncB: w + h visible to all

        if (c + 1 < NCHUNK) {          // refill ef for next chunk (safe after syncB)
            prefetch_ef(S, i0, j0 + JC, ef, adj, t);
            CP_COMMIT();
        }

        // ---- phase 2: acc[i,d] += w[i,j] * h[j,h2,d]   (all smem, f32x2 FMA)
        const float* wbase = &S->w[h2][il0 * WROW];
        const float* hbase = &S->hs[h2 * ODIM + d8 * 4];
#pragma unroll 4
        for (int j = 0; j < JC; j++) {
            const ulonglong2* hb = (const ulonglong2*)(hbase + j * HD);
            const ulonglong2 p0 = hb[0];
            const ulonglong2 p1 = hb[8];   // +128B (odd-chunk half)
#pragma unroll
            for (int r = 0; r < 8; r++) {
                const u64 wp = pack2(wbase[r * WROW + j]);
                ffma2(acc2[r][0], wp, p0.x); ffma2(acc2[r][1], wp, p0.y);
                ffma2(acc2[r][2], wp, p1.x); ffma2(acc2[r][3], wp, p1.y);
            }
        }
        // no trailing barrier: h/w rewritten only after next syncA/syncB.
    }

    // ---- write additive partials (packed)
    float* pa = g_pacc[js];
#pragma unroll
    for (int r = 0; r < 8; r++) {
        ulonglong2* dst =
            (ulonglong2*)(pa + (size_t)(i0 + il0 + r) * HD + h2 * ODIM + d8 * 8);
        ulonglong2 o0; o0.x = acc2[r][0]; o0.y = acc2[r][1];
        ulonglong2 o1; o1.x = acc2[r][2]; o1.y = acc2[r][3];
        dst[0] = o0;
        dst[1] = o1;
    }
    // denom: 16 j-lanes per i-row -> reduce within 16-lane groups
#pragma unroll
    for (int p = 0; p < 4; p++)
#pragma unroll
        for (int h = 0; h < 4; h++) {
            float v = pden[p][h];
#pragma unroll
            for (int o = 8; o; o >>= 1) v += __shfl_xor_sync(0xffffffffu, v, o);
            if (jl == 0)
                g_pden[js][(i0 + p * 16 + ih) * HEADS + h] = v;
        }
}

// ---------------- kernel 4: combine + normalize + layernorm ----------------
__global__ __launch_bounds__(256) void k_final(const float* __restrict__ gamma,
                                               const float* __restrict__ beta,
                                               float* __restrict__ out) {
    __shared__ float rs[4][2], rq[4][2];
    __shared__ float mean_s[4], rstd_s[4];

    const int t = threadIdx.x;
    const int r = t >> 6;
    const int s = t & 63;
    const int n = blockIdx.x * 4 + r;

    float4 v = make_float4(0.f, 0.f, 0.f, 0.f);
#pragma unroll
    for (int sp = 0; sp < JSPLIT; sp++) {
        const float4 p = *(const float4*)&g_pacc[sp][(size_t)n * HD + s * 4];
        v.x += p.x; v.y += p.y; v.z += p.z; v.w += p.w;
    }
    const int h = s >> 4;
    float den = 0.f;
#pragma unroll
    for (int sp = 0; sp < JSPLIT; sp++) den += g_pden[sp][n * HEADS + h];
    const float inv = __frcp_rn(den);
    v.x *= inv; v.y *= inv; v.z *= inv; v.w *= inv;

    float sum = v.x + v.y + v.z + v.w;
    float sq  = v.x * v.x + v.y * v.y + v.z * v.z + v.w * v.w;
#pragma unroll
    for (int o = 16; o; o >>= 1) {
        sum += __shfl_xor_sync(0xffffffffu, sum, o);
        sq  += __shfl_xor_sync(0xffffffffu, sq, o);
    }
    const int half = (t >> 5) & 1;
    if ((t & 31) == 0) { rs[r][half] = sum; rq[r][half] = sq; }
    __syncthreads();
    if (s == 0) {
        const float S = rs[r][0] + rs[r][1];
        const float Q = rq[r][0] + rq[r][1];
        const float m = S * (1.f / HD);
        const float var = Q * (1.f / HD) - m * m;
        mean_s[r] = m;
        rstd_s[r] = rsqrtf(var + 1e-5f);
    }
    __syncthreads();
    const float m   = mean_s[r];
    const float rsd = rstd_s[r];
    const float4 g = ((const float4*)gamma)[s];
    const float4 b = ((const float4*)beta)[s];
    float4 o;
    o.x = (v.x - m) * rsd * g.x + b.x;
    o.y = (v.y - m) * rsd * g.y + b.y;
    o.z = (v.z - m) * rsd * g.z + b.z;
    o.w = (v.w - m) * rsd * g.w + b.w;
    ((float4*)out)[(size_t)n * (HD / 4) + s] = o;
}

// ---------------- launch ----------------------------------------------------
extern "C" void kernel_launch(void* const* d_in, const int* in_sizes, int n_in,
                              void* d_out, int out_size) {
    const float* x      = (const float*)d_in[0];
    const int*   adj    = (const int*)  d_in[1];
    const float* ef     = (const float*)d_in[2];
    const float* W      = (const float*)d_in[3];
    const float* a_src  = (const float*)d_in[4];
    const float* a_dst  = (const float*)d_in[5];
    const float* ep_w   = (const float*)d_in[6];
    const float* ep_b   = (const float*)d_in[7];
    const float* gamma  = (const float*)d_in[8];
    const float* beta   = (const float*)d_in[9];
    float* out = (float*)d_out;

    const int smem_bytes = (int)sizeof(SmemAttn);   // ~78.5 KB
    cudaFuncSetAttribute(k_attn, cudaFuncAttributeMaxDynamicSharedMemorySize,
                         smem_bytes);

    k_proj  <<<NN / 16, 256>>>(x, W);
    k_scores<<<(NN * HEADS) / 256, 256>>>(a_src, a_dst);
    k_attn  <<<dim3(NN / TI, JSPLIT), 256, smem_bytes>>>(ef, adj, ep_w, ep_b);
    k_final <<<NN / 4, 256>>>(gamma, beta, out);
}